// round 16
// baseline (speedup 1.0000x reference)
#include <cuda_runtime.h>
#include <cuda_fp16.h>
#include <cooperative_groups.h>
namespace cg = cooperative_groups;

#define NNODES 50000
#define NHEADS 8
#define EPS 1e-8f
#define ATT_NORM 2.0f
#define MAXB 32            // max 8-edge batches per warp held in the smem ni stash

// Scratch: per-(node, head) running max of nj as float bits (all values >= 0,
// init 0x00000000, so int atomicMax == float max).
__device__ float g_node_max[NNODES * NHEADS];

// Warp-cooperative 8-edge norm: 8 front-issued coalesced LDG.128 per lane,
// shfl_xor(1)+shfl_xor(2) sum-of-squares within 4-lane groups, then 8
// broadcast shuffles so lane L owns (edge base+(L>>3), head L&7) [A] and
// (edge base+4+(L>>3), head L&7) [B].
__device__ __forceinline__ void warp_norms8(const float4* __restrict__ p,
                                            int lane, float& ssA, float& ssB) {
    float4 v[8];
#pragma unroll
    for (int k = 0; k < 8; ++k)
        v[k] = __ldcs(&p[k * 32 + lane]);
    float sq[8];
#pragma unroll
    for (int k = 0; k < 8; ++k) {
        float s = v[k].x * v[k].x + v[k].y * v[k].y
                + v[k].z * v[k].z + v[k].w * v[k].w;
        s += __shfl_xor_sync(0xFFFFFFFFu, s, 1);
        s += __shfl_xor_sync(0xFFFFFFFFu, s, 2);
        sq[k] = s;
    }
    float bc[8];
#pragma unroll
    for (int k = 0; k < 8; ++k)
        bc[k] = __shfl_sync(0xFFFFFFFFu, sq[k], (lane & 7) * 4);
    int ksel = lane >> 3;
    ssA = (ksel == 0) ? bc[0] : (ksel == 1) ? bc[1] : (ksel == 2) ? bc[2] : bc[3];
    ssB = (ksel == 0) ? bc[4] : (ksel == 1) ? bc[5] : (ksel == 2) ? bc[6] : bc[7];
}

// Persistent cooperative kernel. Phase 1: stream x_j (scatter-max) and x_i
// (ni -> smem fp16). grid.sync(). Phase 2: e_ij/index/gather/divide/store.
__global__ void __launch_bounds__(256, 4) fused_kernel(
        const float* __restrict__ e_ij,
        const float4* __restrict__ x_i,
        const float4* __restrict__ x_j,
        const int* __restrict__ index,
        float* __restrict__ out,
        int E, int B_w) {
    __shared__ __half ni_s[8 * MAXB * 64];   // [warp][batch][64] = 32KB
    cg::grid_group grid = cg::this_grid();

    int lane = threadIdx.x & 31;
    int wi = threadIdx.x >> 5;
    int wg = blockIdx.x * 8 + wi;
    int total_warps = gridDim.x * 8;
    int ksel = lane >> 3;
    int h = lane & 7;

    // ---------------- phase 1: norms ----------------
    for (int b = 0; b < B_w; ++b) {
        int wb = wg + b * total_warps;
        long ebase = (long)wb * 8;
        if (ebase >= E) continue;
        if (ebase + 8 <= E) {
            // x_j -> scatter max
            float ssA, ssB;
            warp_norms8(x_j + (size_t)wb * 256, lane, ssA, ssB);
            int nodeA = index[ebase + ksel];
            int nodeB = index[ebase + 4 + ksel];
            float njA = sqrtf(ssA) + EPS;
            float njB = sqrtf(ssB) + EPS;
            if ((unsigned)nodeA < NNODES)
                atomicMax((int*)&g_node_max[nodeA * NHEADS + h], __float_as_int(njA));
            if ((unsigned)nodeB < NNODES)
                atomicMax((int*)&g_node_max[nodeB * NHEADS + h], __float_as_int(njB));
            // x_i -> ni stash (fp16, warp-private slots)
            warp_norms8(x_i + (size_t)wb * 256, lane, ssA, ssB);
            int slot = (wi * MAXB + b) * 64;
            ni_s[slot + lane]      = __float2half(sqrtf(ssA) + EPS);
            ni_s[slot + 32 + lane] = __float2half(sqrtf(ssB) + EPS);
        } else {
            // tail batch (E % 8 != 0): scalar scatter only; ni recomputed in phase 2
            for (long e = ebase; e < E; ++e) {
                if (lane < 8) {
                    const float4* p = &x_j[(size_t)e * 32 + lane * 4];
                    float s = 0.0f;
#pragma unroll
                    for (int q = 0; q < 4; ++q) {
                        float4 t = p[q];
                        s += t.x * t.x + t.y * t.y + t.z * t.z + t.w * t.w;
                    }
                    float nj = sqrtf(s) + EPS;
                    int node = index[e];
                    if ((unsigned)node < NNODES)
                        atomicMax((int*)&g_node_max[node * NHEADS + lane],
                                  __float_as_int(nj));
                }
            }
        }
    }

    // All scatter atomics complete + visible grid-wide.
    grid.sync();

    // ---------------- phase 2: finalize ----------------
    for (int b = 0; b < B_w; ++b) {
        int wb = wg + b * total_warps;
        long ebase = (long)wb * 8;
        if (ebase >= E) continue;
        if (ebase + 8 <= E) {
            float evA = __ldcs(&e_ij[(size_t)ebase * 8 + lane]);
            float evB = __ldcs(&e_ij[(size_t)ebase * 8 + 32 + lane]);
            int nodeA = index[ebase + ksel];
            int nodeB = index[ebase + 4 + ksel];
            int slot = (wi * MAXB + b) * 64;
            float niA = __half2float(ni_s[slot + lane]);
            float niB = __half2float(ni_s[slot + 32 + lane]);

            float mxA = ((unsigned)nodeA < NNODES) ? g_node_max[nodeA * NHEADS + h] : 0.0f;
            float mxB = ((unsigned)nodeB < NNODES) ? g_node_max[nodeB * NHEADS + h] : 0.0f;

            float dA = ATT_NORM * (niA + (mxA + EPS)) + EPS;
            float rA = __fdividef(evA, dA);
            rA = fminf(10.0f, fmaxf(-10.0f, rA));
            __stcs(&out[(size_t)ebase * 8 + lane], rA);

            float dB = ATT_NORM * (niB + (mxB + EPS)) + EPS;
            float rB = __fdividef(evB, dB);
            rB = fminf(10.0f, fmaxf(-10.0f, rB));
            __stcs(&out[(size_t)ebase * 8 + 32 + lane], rB);
        } else {
            for (long e = ebase; e < E; ++e) {
                if (lane < 8) {
                    const float4* p = &x_i[(size_t)e * 32 + lane * 4];
                    float s = 0.0f;
#pragma unroll
                    for (int q = 0; q < 4; ++q) {
                        float4 t = p[q];
                        s += t.x * t.x + t.y * t.y + t.z * t.z + t.w * t.w;
                    }
                    float ni = sqrtf(s) + EPS;
                    int node = index[e];
                    float mx = ((unsigned)node < NNODES)
                             ? g_node_max[node * NHEADS + lane] : 0.0f;
                    float denom = ATT_NORM * (ni + (mx + EPS)) + EPS;
                    float r = __fdividef(e_ij[(size_t)e * 8 + lane], denom);
                    r = fminf(10.0f, fmaxf(-10.0f, r));
                    out[(size_t)e * 8 + lane] = r;
                }
            }
        }
    }
}

// ---------- fallback path (proven R11 kernels) ----------
__global__ void __launch_bounds__(256) scatter_max_kernel(
        const float4* __restrict__ x_j, const int* __restrict__ index, int E) {
    int lane = threadIdx.x & 31;
    int w = (blockIdx.x * blockDim.x + threadIdx.x) >> 5;
    long ebase = (long)w * 8;
    if (ebase >= E) return;
    int ksel = lane >> 3, h = lane & 7;
    if (ebase + 8 <= E) {
        float ssA, ssB;
        warp_norms8(x_j + (size_t)w * 256, lane, ssA, ssB);
        int nodeA = index[ebase + ksel];
        int nodeB = index[ebase + 4 + ksel];
        float njA = sqrtf(ssA) + EPS, njB = sqrtf(ssB) + EPS;
        if ((unsigned)nodeA < NNODES)
            atomicMax((int*)&g_node_max[nodeA * NHEADS + h], __float_as_int(njA));
        if ((unsigned)nodeB < NNODES)
            atomicMax((int*)&g_node_max[nodeB * NHEADS + h], __float_as_int(njB));
    } else {
        for (long e = ebase; e < E; ++e)
            if (lane < 8) {
                const float4* p = &x_j[(size_t)e * 32 + lane * 4];
                float s = 0.0f;
#pragma unroll
                for (int q = 0; q < 4; ++q) {
                    float4 t = p[q];
                    s += t.x * t.x + t.y * t.y + t.z * t.z + t.w * t.w;
                }
                float nj = sqrtf(s) + EPS;
                int node = index[e];
                if ((unsigned)node < NNODES)
                    atomicMax((int*)&g_node_max[node * NHEADS + lane],
                              __float_as_int(nj));
            }
    }
}

__global__ void __launch_bounds__(256) finalize_kernel(
        const float* __restrict__ e_ij, const float4* __restrict__ x_i,
        const int* __restrict__ index, float* __restrict__ out, int E) {
    int lane = threadIdx.x & 31;
    int w = (blockIdx.x * blockDim.x + threadIdx.x) >> 5;
    long ebase = (long)w * 8;
    if (ebase >= E) return;
    int ksel = lane >> 3, h = lane & 7;
    if (ebase + 8 <= E) {
        float ssA, ssB;
        warp_norms8(x_i + (size_t)w * 256, lane, ssA, ssB);
        float evA = __ldcs(&e_ij[(size_t)ebase * 8 + lane]);
        float evB = __ldcs(&e_ij[(size_t)ebase * 8 + 32 + lane]);
        int nodeA = index[ebase + ksel];
        int nodeB = index[ebase + 4 + ksel];
        float mxA = ((unsigned)nodeA < NNODES) ? g_node_max[nodeA * NHEADS + h] : 0.0f;
        float mxB = ((unsigned)nodeB < NNODES) ? g_node_max[nodeB * NHEADS + h] : 0.0f;
        float dA = ATT_NORM * ((sqrtf(ssA) + EPS) + (mxA + EPS)) + EPS;
        float rA = __fdividef(evA, dA);
        rA = fminf(10.0f, fmaxf(-10.0f, rA));
        __stcs(&out[(size_t)ebase * 8 + lane], rA);
        float dB = ATT_NORM * ((sqrtf(ssB) + EPS) + (mxB + EPS)) + EPS;
        float rB = __fdividef(evB, dB);
        rB = fminf(10.0f, fmaxf(-10.0f, rB));
        __stcs(&out[(size_t)ebase * 8 + 32 + lane], rB);
    } else {
        for (long e = ebase; e < E; ++e)
            if (lane < 8) {
                const float4* p = &x_i[(size_t)e * 32 + lane * 4];
                float s = 0.0f;
#pragma unroll
                for (int q = 0; q < 4; ++q) {
                    float4 t = p[q];
                    s += t.x * t.x + t.y * t.y + t.z * t.z + t.w * t.w;
                }
                float ni = sqrtf(s) + EPS;
                int node = index[e];
                float mx = ((unsigned)node < NNODES)
                         ? g_node_max[node * NHEADS + lane] : 0.0f;
                float denom = ATT_NORM * (ni + (mx + EPS)) + EPS;
                float r = __fdividef(e_ij[(size_t)e * 8 + lane], denom);
                r = fminf(10.0f, fmaxf(-10.0f, r));
                out[(size_t)e * 8 + lane] = r;
            }
    }
}

extern "C" void kernel_launch(void* const* d_in, const int* in_sizes, int n_in,
                              void* d_out, int out_size) {
    // metadata order: e_ij [E,H] f32, x_i [E,H,D] f32, x_j [E,H,D] f32, index [E] i32
    const float*  e_ij  = (const float*)d_in[0];
    const float4* x_i   = (const float4*)d_in[1];
    const float4* x_j   = (const float4*)d_in[2];
    const int*    index = (const int*)d_in[3];
    float*        out   = (float*)d_out;

    int E = in_sizes[0] / NHEADS;        // 800,000

    void* nm_ptr = nullptr;
    cudaGetSymbolAddress(&nm_ptr, g_node_max);
    cudaMemsetAsync(nm_ptr, 0, sizeof(float) * NNODES * NHEADS, 0);

    // Size the cooperative grid: one full wave.
    int dev = 0, sms = 0, bpm = 0;
    cudaGetDevice(&dev);
    cudaDeviceGetAttribute(&sms, cudaDevAttrMultiProcessorCount, dev);
    cudaOccupancyMaxActiveBlocksPerMultiprocessor(&bpm, fused_kernel, 256, 0);

    int grid = sms * bpm;
    int total_warps = grid * 8;
    int nbatch = (E + 7) / 8;
    int B_w = (total_warps > 0) ? (nbatch + total_warps - 1) / total_warps : MAXB + 1;

    if (bpm > 0 && B_w <= MAXB) {
        void* args[] = {(void*)&e_ij, (void*)&x_i, (void*)&x_j,
                        (void*)&index, (void*)&out, (void*)&E, (void*)&B_w};
        cudaLaunchCooperativeKernel((void*)fused_kernel,
                                    dim3(grid), dim3(256), args, 0, 0);
    } else {
        // Fallback: proven two-kernel path.
        const int B = 256;
        int warps8 = (E + 7) / 8;
        int blocks8 = (warps8 + (B / 32) - 1) / (B / 32);
        scatter_max_kernel<<<blocks8, B>>>(x_j, index, E);
        finalize_kernel<<<blocks8, B>>>(e_ij, x_i, index, out, E);
    }
}

// round 17
// speedup vs baseline: 1.1408x; 1.1408x over previous
#include <cuda_runtime.h>

#define NNODES 50000
#define NHEADS 8
#define EPS 1e-8f
#define ATT_NORM 2.0f

// Scratch: per-(node, head) running max of nj as float bits (all values >= 0,
// init 0x00000000, so int atomicMax == float max).
__device__ float g_node_max[NNODES * NHEADS];

// Warp-cooperative 16-edge sum-of-squares:
//  - 16 front-issued, perfectly coalesced 512B warp loads (4KB in flight/warp)
//  - shfl_xor(1)+shfl_xor(2) completes each 16-dim norm within 4-lane groups
//  - 16 broadcast shuffles redistribute so lane L owns (edge base+4g+(L>>3),
//    head L&7) for g=0..3, returned in ss[4].
__device__ __forceinline__ void warp_norms16(const float4* __restrict__ p,
                                             int lane, float ss[4]) {
    float4 v[16];
#pragma unroll
    for (int k = 0; k < 16; ++k)
        v[k] = __ldcs(&p[k * 32 + lane]);
    float sq[16];
#pragma unroll
    for (int k = 0; k < 16; ++k) {
        float s = v[k].x * v[k].x + v[k].y * v[k].y
                + v[k].z * v[k].z + v[k].w * v[k].w;
        s += __shfl_xor_sync(0xFFFFFFFFu, s, 1);
        s += __shfl_xor_sync(0xFFFFFFFFu, s, 2);
        sq[k] = s;
    }
    int src = (lane & 7) * 4;
    int ksel = lane >> 3;
#pragma unroll
    for (int g = 0; g < 4; ++g) {
        float b0 = __shfl_sync(0xFFFFFFFFu, sq[g * 4 + 0], src);
        float b1 = __shfl_sync(0xFFFFFFFFu, sq[g * 4 + 1], src);
        float b2 = __shfl_sync(0xFFFFFFFFu, sq[g * 4 + 2], src);
        float b3 = __shfl_sync(0xFFFFFFFFu, sq[g * 4 + 3], src);
        ss[g] = (ksel == 0) ? b0 : (ksel == 1) ? b1 : (ksel == 2) ? b2 : b3;
    }
}

__global__ void __launch_bounds__(256, 2) scatter_max_kernel(
        const float4* __restrict__ x_j,
        const int* __restrict__ index,
        int E) {
    int lane = threadIdx.x & 31;
    int w = (blockIdx.x * blockDim.x + threadIdx.x) >> 5;
    long ebase = (long)w * 16;
    if (ebase >= E) return;

    int ksel = lane >> 3;
    int h = lane & 7;

    if (ebase + 16 <= E) {
        float ss[4];
        warp_norms16(x_j + (size_t)w * 512, lane, ss);
        int node[4];
#pragma unroll
        for (int g = 0; g < 4; ++g)
            node[g] = index[ebase + g * 4 + ksel];
#pragma unroll
        for (int g = 0; g < 4; ++g) {
            float nj = sqrtf(ss[g]) + EPS;
            if ((unsigned)node[g] < NNODES)
                atomicMax((int*)&g_node_max[node[g] * NHEADS + h],
                          __float_as_int(nj));
        }
    } else {
        // tail: per-(e,h) scalar path
        for (long e = ebase; e < E; ++e) {
            if (lane < 8) {
                const float4* p = &x_j[(size_t)e * 32 + lane * 4];
                float s = 0.0f;
#pragma unroll
                for (int q = 0; q < 4; ++q) {
                    float4 t = p[q];
                    s += t.x * t.x + t.y * t.y + t.z * t.z + t.w * t.w;
                }
                float nj = sqrtf(s) + EPS;
                int nd = index[e];
                if ((unsigned)nd < NNODES)
                    atomicMax((int*)&g_node_max[nd * NHEADS + lane],
                              __float_as_int(nj));
            }
        }
    }
}

__global__ void __launch_bounds__(256, 2) finalize_kernel(
        const float* __restrict__ e_ij,
        const float4* __restrict__ x_i,
        const int* __restrict__ index,
        float* __restrict__ out,
        int E) {
    int lane = threadIdx.x & 31;
    int w = (blockIdx.x * blockDim.x + threadIdx.x) >> 5;
    long ebase = (long)w * 16;
    if (ebase >= E) return;

    int ksel = lane >> 3;
    int h = lane & 7;

    if (ebase + 16 <= E) {
        float ss[4];
        warp_norms16(x_i + (size_t)w * 512, lane, ss);

        float ev[4];
        int node[4];
#pragma unroll
        for (int g = 0; g < 4; ++g)
            ev[g] = __ldcs(&e_ij[(size_t)ebase * 8 + g * 32 + lane]);
#pragma unroll
        for (int g = 0; g < 4; ++g)
            node[g] = index[ebase + g * 4 + ksel];

        float mx[4];
#pragma unroll
        for (int g = 0; g < 4; ++g)
            mx[g] = ((unsigned)node[g] < NNODES)
                  ? g_node_max[node[g] * NHEADS + h] : 0.0f;

#pragma unroll
        for (int g = 0; g < 4; ++g) {
            float ni = sqrtf(ss[g]) + EPS;
            float denom = ATT_NORM * (ni + (mx[g] + EPS)) + EPS;
            float r = __fdividef(ev[g], denom);
            r = fminf(10.0f, fmaxf(-10.0f, r));
            __stcs(&out[(size_t)ebase * 8 + g * 32 + lane], r);
        }
    } else {
        // tail: per-(e,h) scalar path
        for (long e = ebase; e < E; ++e) {
            if (lane < 8) {
                const float4* p = &x_i[(size_t)e * 32 + lane * 4];
                float s = 0.0f;
#pragma unroll
                for (int q = 0; q < 4; ++q) {
                    float4 t = p[q];
                    s += t.x * t.x + t.y * t.y + t.z * t.z + t.w * t.w;
                }
                float ni = sqrtf(s) + EPS;
                int nd = index[e];
                float m = ((unsigned)nd < NNODES)
                        ? g_node_max[nd * NHEADS + lane] : 0.0f;
                float denom = ATT_NORM * (ni + (m + EPS)) + EPS;
                float r = __fdividef(e_ij[(size_t)e * 8 + lane], denom);
                r = fminf(10.0f, fmaxf(-10.0f, r));
                out[(size_t)e * 8 + lane] = r;
            }
        }
    }
}

extern "C" void kernel_launch(void* const* d_in, const int* in_sizes, int n_in,
                              void* d_out, int out_size) {
    // metadata order: e_ij [E,H] f32, x_i [E,H,D] f32, x_j [E,H,D] f32, index [E] i32
    const float*  e_ij  = (const float*)d_in[0];
    const float4* x_i   = (const float4*)d_in[1];
    const float4* x_j   = (const float4*)d_in[2];
    const int*    index = (const int*)d_in[3];
    float*        out   = (float*)d_out;

    int E = in_sizes[0] / NHEADS;        // 800,000

    void* nm_ptr = nullptr;
    cudaGetSymbolAddress(&nm_ptr, g_node_max);
    cudaMemsetAsync(nm_ptr, 0, sizeof(float) * NNODES * NHEADS, 0);

    const int B = 256;                                   // 8 warps/block
    int warps16 = (E + 15) / 16;                         // 50000 (exact, no tail)
    int blocks16 = (warps16 + (B / 32) - 1) / (B / 32);  // 6250

    scatter_max_kernel<<<blocks16, B>>>(x_j, index, E);
    finalize_kernel<<<blocks16, B>>>(e_ij, x_i, index, out, E);
}